// round 13
// baseline (speedup 1.0000x reference)
#include <cuda_runtime.h>
#include <cstdint>

// CapsuleRouting R12: register-direct LDG pipeline (no cp.async, no u staging)
//  - CTA = (b, x-tile of 8); 144 CTAs, 256 threads; warp owns 18 B
//  - chunk = one B in REGISTERS (double-buffered ua/ub, 16 float4 each);
//    loads for j+1 issued before compute(j) -> scoreboard-grade overlap
//  - serpentine pass order (pass 1 reversed) for L2 turnaround reuse
//  - v in smem (read in dot); accumulate reuses resident u registers
//  - r eliminated (logits linear in v: pass2 dots against w = v0+v1); `a` ignored

#define C_N   16
#define P_N   16
#define F2    144
#define XT    8
#define NTILE 18
#define NW    8
#define BPW   18
#define PLANE 132                     // 16C rows of (16p x 8x) + pad
#define PART_FL (C_N * PLANE)         // 2112 floats per warp partial
#define V_OFF   (NW * PART_FL)        // 16896
#define SMEM_FL (V_OFF + PART_FL)     // 19008
#define SMEM_BYTES (SMEM_FL * 4)      // 76032
#define BSTRIDE (C_N * P_N * F2)      // 36864 floats per B
#define V_ELEMS (8 * C_N * P_N * F2)  // 294912

// serpentine B order: pass 1 reversed
#define BIDX(pass, j) (((pass) == 1) ? (BPW - 1 - (j)) : (j))

// load one chunk (this lane's 16 p-rows, float4 each) straight to registers
__device__ __forceinline__ void ldchunk(const float* __restrict__ g, float4* r) {
#pragma unroll
    for (int p = 0; p < 16; p++)
        r[p] = *(const float4*)(g + p * F2);
}

__global__ void __launch_bounds__(256, 1)
caps_route_kernel(const float* __restrict__ u, float* __restrict__ out) {
    extern __shared__ float sm[];
    float* v_s = sm + V_OFF;

    const int t = threadIdx.x;
    const int w = t >> 5, lane = t & 31;
    const int Cc = lane & 15, zh = lane >> 4;

    const int b  = blockIdx.x / NTILE;
    const int x0 = (blockIdx.x % NTILE) * XT;

    // lane's global base: warp B-slice + its C row block + x-quad
    const float* laneg = u + ((size_t)b * 144 + w * BPW) * BSTRIDE
                           + (size_t)Cc * P_N * F2 + x0 + zh * 4;
    float* wpart = sm + w * PART_FL;
    const int ld_off = Cc * PLANE + zh * 4;    // + p*8

    float4 ua[16], ub[16];
    ldchunk(laneg, ua);                        // pass0 chunk0

    for (int pass = 0; pass < 3; pass++) {
        float4 sreg[16];
#pragma unroll
        for (int p = 0; p < 16; p++) sreg[p] = make_float4(0.f, 0.f, 0.f, 0.f);

#pragma unroll 2
        for (int j = 0; j < BPW; j++) {
            float4* cur = (j & 1) ? ub : ua;
            float4* nxt = (j & 1) ? ua : ub;
            if (j + 1 < BPW)   // issue next chunk's loads BEFORE compute
                ldchunk(laneg + (size_t)BIDX(pass, j + 1) * BSTRIDE, nxt);

            if (pass == 0) {
#pragma unroll
                for (int p = 0; p < 16; p++) {
                    sreg[p].x += cur[p].x; sreg[p].y += cur[p].y;
                    sreg[p].z += cur[p].z; sreg[p].w += cur[p].w;
                }
            } else {
                float4 d = make_float4(0.f, 0.f, 0.f, 0.f);
#pragma unroll
                for (int p = 0; p < 16; p++) {
                    float4 v4 = *(const float4*)&v_s[ld_off + p * 8];
                    d.x = fmaf(cur[p].x, v4.x, d.x);
                    d.y = fmaf(cur[p].y, v4.y, d.y);
                    d.z = fmaf(cur[p].z, v4.z, d.z);
                    d.w = fmaf(cur[p].w, v4.w, d.w);
                }
                // softmax over C: 16-lane shuffle groups, 4 chains ILP
                float4 e = make_float4(__expf(d.x), __expf(d.y),
                                       __expf(d.z), __expf(d.w));
                float4 ss = e;
#pragma unroll
                for (int m = 1; m < 16; m <<= 1) {
                    ss.x += __shfl_xor_sync(0xffffffffu, ss.x, m);
                    ss.y += __shfl_xor_sync(0xffffffffu, ss.y, m);
                    ss.z += __shfl_xor_sync(0xffffffffu, ss.z, m);
                    ss.w += __shfl_xor_sync(0xffffffffu, ss.w, m);
                }
                float4 cc = make_float4(__fdividef(e.x, ss.x),
                                        __fdividef(e.y, ss.y),
                                        __fdividef(e.z, ss.z),
                                        __fdividef(e.w, ss.w));
#pragma unroll
                for (int p = 0; p < 16; p++) {   // u still register-resident
                    sreg[p].x = fmaf(cc.x, cur[p].x, sreg[p].x);
                    sreg[p].y = fmaf(cc.y, cur[p].y, sreg[p].y);
                    sreg[p].z = fmaf(cc.z, cur[p].z, sreg[p].z);
                    sreg[p].w = fmaf(cc.w, cur[p].w, sreg[p].w);
                }
            }
        }

        // ---- per-warp partial s -> own smem region ----
        if (pass == 0) {
#pragma unroll
            for (int p = 0; p < 16; p++) {
                sreg[p].x *= 0.0625f; sreg[p].y *= 0.0625f;
                sreg[p].z *= 0.0625f; sreg[p].w *= 0.0625f;
            }
        }
#pragma unroll
        for (int p = 0; p < 16; p++)
            *(float4*)&wpart[ld_off + p * 8] = sreg[p];

        if (pass < 2)   // next pass chunk0 (serpentine: L2-hot) hides the barrier
            ldchunk(laneg + (size_t)BIDX(pass + 1, 0) * BSTRIDE, ua);
        __syncthreads();

        // ---- cross-warp reduce + squash: thread t = (Cc2 = t>>4, p2 = t&15)
        {
            const int Cc2 = t >> 4, p2 = t & 15;
            const int roff = Cc2 * PLANE + p2 * 8;
            float4 sa = make_float4(0.f, 0.f, 0.f, 0.f);   // z 0..3
            float4 sb = make_float4(0.f, 0.f, 0.f, 0.f);   // z 4..7
#pragma unroll
            for (int w2 = 0; w2 < NW; w2++) {
                float4 a4 = *(const float4*)&sm[w2 * PART_FL + roff];
                float4 b4 = *(const float4*)&sm[w2 * PART_FL + roff + 4];
                sa.x += a4.x; sa.y += a4.y; sa.z += a4.z; sa.w += a4.w;
                sb.x += b4.x; sb.y += b4.y; sb.z += b4.z; sb.w += b4.w;
            }
            float4 na = make_float4(sa.x * sa.x, sa.y * sa.y,
                                    sa.z * sa.z, sa.w * sa.w);
            float4 nb = make_float4(sb.x * sb.x, sb.y * sb.y,
                                    sb.z * sb.z, sb.w * sb.w);
#pragma unroll
            for (int m = 1; m < 16; m <<= 1) {
                na.x += __shfl_xor_sync(0xffffffffu, na.x, m);
                na.y += __shfl_xor_sync(0xffffffffu, na.y, m);
                na.z += __shfl_xor_sync(0xffffffffu, na.z, m);
                na.w += __shfl_xor_sync(0xffffffffu, na.w, m);
                nb.x += __shfl_xor_sync(0xffffffffu, nb.x, m);
                nb.y += __shfl_xor_sync(0xffffffffu, nb.y, m);
                nb.z += __shfl_xor_sync(0xffffffffu, nb.z, m);
                nb.w += __shfl_xor_sync(0xffffffffu, nb.w, m);
            }
            float4 ka = make_float4(sqrtf(na.x) / (1.f + na.x),
                                    sqrtf(na.y) / (1.f + na.y),
                                    sqrtf(na.z) / (1.f + na.z),
                                    sqrtf(na.w) / (1.f + na.w));
            float4 kb = make_float4(sqrtf(nb.x) / (1.f + nb.x),
                                    sqrtf(nb.y) / (1.f + nb.y),
                                    sqrtf(nb.z) / (1.f + nb.z),
                                    sqrtf(nb.w) / (1.f + nb.w));
            float4 va = make_float4(sa.x * ka.x, sa.y * ka.y,
                                    sa.z * ka.z, sa.w * ka.w);
            float4 vb = make_float4(sb.x * kb.x, sb.y * kb.y,
                                    sb.z * kb.z, sb.w * kb.w);

            if (pass < 2) {
                if (pass == 1) {   // store w = v0 + v1 (logits linear in v)
                    float4 oa = *(const float4*)&v_s[roff];
                    float4 ob = *(const float4*)&v_s[roff + 4];
                    va.x += oa.x; va.y += oa.y; va.z += oa.z; va.w += oa.w;
                    vb.x += ob.x; vb.y += ob.y; vb.z += ob.z; vb.w += ob.w;
                }
                *(float4*)&v_s[roff]     = va;
                *(float4*)&v_s[roff + 4] = vb;
            } else {
                float* og = out + (((size_t)(b * C_N + Cc2)) * P_N + p2) * F2 + x0;
                *(float4*)og       = va;
                *(float4*)(og + 4) = vb;
                if (p2 == 0) {
                    float* oa = out + (size_t)V_ELEMS
                              + ((size_t)(b * C_N + Cc2)) * F2 + x0;
                    *(float4*)oa = make_float4(na.x / (1.f + na.x),
                                               na.y / (1.f + na.y),
                                               na.z / (1.f + na.z),
                                               na.w / (1.f + na.w));
                    *(float4*)(oa + 4) = make_float4(nb.x / (1.f + nb.x),
                                                     nb.y / (1.f + nb.y),
                                                     nb.z / (1.f + nb.z),
                                                     nb.w / (1.f + nb.w));
                }
            }
        }
        __syncthreads();   // v_s visible before next pass's dot reads it
    }
}

extern "C" void kernel_launch(void* const* d_in, const int* in_sizes, int n_in,
                              void* d_out, int out_size) {
    const float* u = (const float*)d_in[0];   // (8,144,16,16,12,12) f32
    float* out = (float*)d_out;               // v (8,16,16,144) then a_out (8,16,144)

    cudaFuncSetAttribute(caps_route_kernel,
                         cudaFuncAttributeMaxDynamicSharedMemorySize, SMEM_BYTES);
    caps_route_kernel<<<8 * NTILE, 256, SMEM_BYTES>>>(u, out);
}

// round 14
// speedup vs baseline: 1.2599x; 1.2599x over previous
#include <cuda_runtime.h>
#include <cstdint>

// CapsuleRouting R13 = R11 + software-pipelined inner loop (passes 1-2):
//  dot(chunk j+1) is computed BEFORE softmax+accum(chunk j), interleaving the
//  LDS/FMA chain of the next chunk with the shuffle/exp chain of the current.
//  - CTA = (b, x-tile of 8); 144 CTAs, 256 threads; warp owns 18 B
//  - per-warp 3-stage cp.async pipeline, no __syncthreads in main loop
//  - serpentine pass order (pass 1 reversed) for L2 turnaround reuse
//  - r eliminated (logits linear in v: pass2 dots against w = v0+v1); `a` ignored

#define C_N   16
#define P_N   16
#define F2    144
#define XT    8
#define NTILE 18
#define NW    8
#define BPW   18                    // B per warp
#define PLANE 132                   // P_N*XT + 4 pad
#define STG_FL (C_N * PLANE)        // 2112 floats per stage (one B)
#define NSTG  3
#define WSTRIDE (NSTG * STG_FL)     // 6336 per warp
#define U_FL  (NW * WSTRIDE)        // 50688
#define V_OFF U_FL
#define SMEM_FL (U_FL + STG_FL)     // 52800
#define SMEM_BYTES (SMEM_FL * 4)    // 211200 -> 1 CTA/SM
#define BSTRIDE (C_N * P_N * F2)    // 36864 floats per B
#define V_ELEMS (8 * C_N * P_N * F2)

// serpentine B order: pass 1 reversed
#define BIDX(pass, j) (((pass) == 1) ? (BPW - 1 - (j)) : (j))

__device__ __forceinline__ void cp_async16(uint32_t s, const float* g) {
    asm volatile("cp.async.cg.shared.global [%0], [%1], 16;" :: "r"(s), "l"(g));
}

// load one B-value (16C x 16p rows of 32B) into a warp stage; 16 cp.async/lane
__device__ __forceinline__ void prefetch_B(const float* __restrict__ gB,
                                           uint32_t dst, int lane) {
    const int pl = lane >> 1, h = lane & 1;
    const float* g = gB + (size_t)pl * F2 + h * 4;
    uint32_t d = dst + 4u * (pl * XT + h * 4);
#pragma unroll
    for (int k = 0; k < 16; k++)     // k = C index
        cp_async16(d + 4u * (k * PLANE), g + (size_t)k * (P_N * F2));
    asm volatile("cp.async.commit_group;");
}

__global__ void __launch_bounds__(256, 1)
caps_route_kernel(const float* __restrict__ u, float* __restrict__ out) {
    extern __shared__ float sm[];
    const uint32_t smb = (uint32_t)__cvta_generic_to_shared(sm);
    float* v_s = sm + V_OFF;

    const int t = threadIdx.x;
    const int w = t >> 5, lane = t & 31;
    const int Cc = lane & 15, zh = lane >> 4;

    const int b  = blockIdx.x / NTILE;
    const int x0 = (blockIdx.x % NTILE) * XT;

    const float* ubW = u + ((size_t)b * 144 + w * BPW) * BSTRIDE + x0;
    const uint32_t wbase = smb + 4u * (w * WSTRIDE);
    float* wstage0 = sm + w * WSTRIDE;
    const int ld_off = Cc * PLANE + zh * 4;        // + p*8 per p

    for (int pass = 0; pass < 3; pass++) {
        float4 vreg[16];
        if (pass) {
#pragma unroll
            for (int p = 0; p < 16; p++)
                vreg[p] = *(const float4*)&v_s[ld_off + p * 8];
        }
        float4 sreg[16];
#pragma unroll
        for (int p = 0; p < 16; p++) sreg[p] = make_float4(0.f, 0.f, 0.f, 0.f);

        prefetch_B(ubW + (size_t)BIDX(pass, 0) * BSTRIDE, wbase,                lane);
        prefetch_B(ubW + (size_t)BIDX(pass, 1) * BSTRIDE, wbase + 4u * STG_FL,  lane);
        prefetch_B(ubW + (size_t)BIDX(pass, 2) * BSTRIDE, wbase + 8u * STG_FL,  lane);

        if (pass == 0) {
            // simple accumulate loop (no softmax chain)
            for (int j = 0; j < BPW; j++) {
                if      (j <= BPW - 4) asm volatile("cp.async.wait_group 2;");
                else if (j == BPW - 3) asm volatile("cp.async.wait_group 2;");
                else if (j == BPW - 2) asm volatile("cp.async.wait_group 1;");
                else                   asm volatile("cp.async.wait_group 0;");
                __syncwarp();
                const float* st = sm + w * WSTRIDE + (j % NSTG) * STG_FL + ld_off;
#pragma unroll
                for (int p = 0; p < 16; p++) {
                    float4 u4 = *(const float4*)&st[p * 8];
                    sreg[p].x += u4.x; sreg[p].y += u4.y;
                    sreg[p].z += u4.z; sreg[p].w += u4.w;
                }
                if (j + 3 < BPW)   // stage j%3 just consumed
                    prefetch_B(ubW + (size_t)BIDX(pass, j + 3) * BSTRIDE,
                               wbase + 4u * ((j % NSTG) * STG_FL), lane);
            }
        } else {
            // ---- software-pipelined: dot(j+1) overlaps softmax+accum(j) ----
            asm volatile("cp.async.wait_group 2;");
            __syncwarp();
            float4 d;
            {   // dot of chunk 0
                const float* st = sm + w * WSTRIDE + 0 * STG_FL + ld_off;
                d = make_float4(0.f, 0.f, 0.f, 0.f);
#pragma unroll
                for (int p = 0; p < 16; p++) {
                    float4 u4 = *(const float4*)&st[p * 8];
                    d.x = fmaf(u4.x, vreg[p].x, d.x);
                    d.y = fmaf(u4.y, vreg[p].y, d.y);
                    d.z = fmaf(u4.z, vreg[p].z, d.z);
                    d.w = fmaf(u4.w, vreg[p].w, d.w);
                }
            }
            for (int j = 0; j < BPW; j++) {
                float4 dn = make_float4(0.f, 0.f, 0.f, 0.f);
                if (j + 1 < BPW) {
                    if (j <= BPW - 3) asm volatile("cp.async.wait_group 1;");
                    else              asm volatile("cp.async.wait_group 0;");
                    __syncwarp();
                    const float* stn = sm + w * WSTRIDE
                                     + ((j + 1) % NSTG) * STG_FL + ld_off;
#pragma unroll
                    for (int p = 0; p < 16; p++) {
                        float4 u4 = *(const float4*)&stn[p * 8];
                        dn.x = fmaf(u4.x, vreg[p].x, dn.x);
                        dn.y = fmaf(u4.y, vreg[p].y, dn.y);
                        dn.z = fmaf(u4.z, vreg[p].z, dn.z);
                        dn.w = fmaf(u4.w, vreg[p].w, dn.w);
                    }
                }
                // softmax over C for chunk j (16-lane shuffle groups)
                float4 e = make_float4(__expf(d.x), __expf(d.y),
                                       __expf(d.z), __expf(d.w));
                float4 ss = e;
#pragma unroll
                for (int m = 1; m < 16; m <<= 1) {
                    ss.x += __shfl_xor_sync(0xffffffffu, ss.x, m);
                    ss.y += __shfl_xor_sync(0xffffffffu, ss.y, m);
                    ss.z += __shfl_xor_sync(0xffffffffu, ss.z, m);
                    ss.w += __shfl_xor_sync(0xffffffffu, ss.w, m);
                }
                float4 cc = make_float4(__fdividef(e.x, ss.x),
                                        __fdividef(e.y, ss.y),
                                        __fdividef(e.z, ss.z),
                                        __fdividef(e.w, ss.w));
                const float* st = sm + w * WSTRIDE + (j % NSTG) * STG_FL + ld_off;
#pragma unroll
                for (int p = 0; p < 16; p++) {
                    float4 u4 = *(const float4*)&st[p * 8];
                    sreg[p].x = fmaf(cc.x, u4.x, sreg[p].x);
                    sreg[p].y = fmaf(cc.y, u4.y, sreg[p].y);
                    sreg[p].z = fmaf(cc.z, u4.z, sreg[p].z);
                    sreg[p].w = fmaf(cc.w, u4.w, sreg[p].w);
                }
                if (j + 3 < BPW)   // stage j%3 fully consumed now
                    prefetch_B(ubW + (size_t)BIDX(pass, j + 3) * BSTRIDE,
                               wbase + 4u * ((j % NSTG) * STG_FL), lane);
                d = dn;
            }
        }

        // ---- per-warp partial s -> own stage 0 (own pipeline drained) ----
        if (pass == 0) {
#pragma unroll
            for (int p = 0; p < 16; p++) {
                sreg[p].x *= 0.0625f; sreg[p].y *= 0.0625f;
                sreg[p].z *= 0.0625f; sreg[p].w *= 0.0625f;
            }
        }
#pragma unroll
        for (int p = 0; p < 16; p++)
            *(float4*)&wstage0[ld_off + p * 8] = sreg[p];
        __syncthreads();

        // ---- cross-warp reduce + squash: thread t = (Cc2 = t>>4, p2 = t&15)
        {
            const int Cc2 = t >> 4, p2 = t & 15;
            const int roff = Cc2 * PLANE + p2 * 8;
            float4 sa = make_float4(0.f, 0.f, 0.f, 0.f);   // z 0..3
            float4 sb = make_float4(0.f, 0.f, 0.f, 0.f);   // z 4..7
#pragma unroll
            for (int w2 = 0; w2 < NW; w2++) {
                float4 a4 = *(const float4*)&sm[w2 * WSTRIDE + roff];
                float4 b4 = *(const float4*)&sm[w2 * WSTRIDE + roff + 4];
                sa.x += a4.x; sa.y += a4.y; sa.z += a4.z; sa.w += a4.w;
                sb.x += b4.x; sb.y += b4.y; sb.z += b4.z; sb.w += b4.w;
            }
            float4 na = make_float4(sa.x * sa.x, sa.y * sa.y,
                                    sa.z * sa.z, sa.w * sa.w);
            float4 nb = make_float4(sb.x * sb.x, sb.y * sb.y,
                                    sb.z * sb.z, sb.w * sb.w);
#pragma unroll
            for (int m = 1; m < 16; m <<= 1) {
                na.x += __shfl_xor_sync(0xffffffffu, na.x, m);
                na.y += __shfl_xor_sync(0xffffffffu, na.y, m);
                na.z += __shfl_xor_sync(0xffffffffu, na.z, m);
                na.w += __shfl_xor_sync(0xffffffffu, na.w, m);
                nb.x += __shfl_xor_sync(0xffffffffu, nb.x, m);
                nb.y += __shfl_xor_sync(0xffffffffu, nb.y, m);
                nb.z += __shfl_xor_sync(0xffffffffu, nb.z, m);
                nb.w += __shfl_xor_sync(0xffffffffu, nb.w, m);
            }
            float4 ka = make_float4(sqrtf(na.x) / (1.f + na.x),
                                    sqrtf(na.y) / (1.f + na.y),
                                    sqrtf(na.z) / (1.f + na.z),
                                    sqrtf(na.w) / (1.f + na.w));
            float4 kb = make_float4(sqrtf(nb.x) / (1.f + nb.x),
                                    sqrtf(nb.y) / (1.f + nb.y),
                                    sqrtf(nb.z) / (1.f + nb.z),
                                    sqrtf(nb.w) / (1.f + nb.w));
            float4 va = make_float4(sa.x * ka.x, sa.y * ka.y,
                                    sa.z * ka.z, sa.w * ka.w);
            float4 vb = make_float4(sb.x * kb.x, sb.y * kb.y,
                                    sb.z * kb.z, sb.w * kb.w);

            if (pass < 2) {
                if (pass == 1) {   // store w = v0 + v1 (logits linear in v)
                    float4 oa = *(const float4*)&v_s[roff];
                    float4 ob = *(const float4*)&v_s[roff + 4];
                    va.x += oa.x; va.y += oa.y; va.z += oa.z; va.w += oa.w;
                    vb.x += ob.x; vb.y += ob.y; vb.z += ob.z; vb.w += ob.w;
                }
                *(float4*)&v_s[roff]     = va;
                *(float4*)&v_s[roff + 4] = vb;
            } else {
                float* og = out + (((size_t)(b * C_N + Cc2)) * P_N + p2) * F2 + x0;
                *(float4*)og       = va;
                *(float4*)(og + 4) = vb;
                if (p2 == 0) {
                    float* oa = out + (size_t)V_ELEMS
                              + ((size_t)(b * C_N + Cc2)) * F2 + x0;
                    *(float4*)oa = make_float4(na.x / (1.f + na.x),
                                               na.y / (1.f + na.y),
                                               na.z / (1.f + na.z),
                                               na.w / (1.f + na.w));
                    *(float4*)(oa + 4) = make_float4(nb.x / (1.f + nb.x),
                                                     nb.y / (1.f + nb.y),
                                                     nb.z / (1.f + nb.z),
                                                     nb.w / (1.f + nb.w));
                }
            }
        }
        __syncthreads();   // v visible; stage-0 partials consumed before reuse
    }
}

extern "C" void kernel_launch(void* const* d_in, const int* in_sizes, int n_in,
                              void* d_out, int out_size) {
    const float* u = (const float*)d_in[0];   // (8,144,16,16,12,12) f32
    float* out = (float*)d_out;               // v (8,16,16,144) then a_out (8,16,144)

    cudaFuncSetAttribute(caps_route_kernel,
                         cudaFuncAttributeMaxDynamicSharedMemorySize, SMEM_BYTES);
    caps_route_kernel<<<8 * NTILE, 256, SMEM_BYTES>>>(u, out);
}